// round 10
// baseline (speedup 1.0000x reference)
#include <cuda_runtime.h>
#include <cuda_fp16.h>
#include <cstdint>

#define M_TOT 8192
#define N_TOT 4096
#define K_TOT 4096

#define BM 128
#define BN 256
#define BK 64
#define NT (K_TOT / BK)          // 64
#define STAGES 4

#define LDA 72                   // 64 + 8 halves; 144B = 9*16B (odd) conflict-free
#define LDB 264                  // 256 + 8 halves; 528B = 33*16B (odd) conflict-free
#define A_STAGE_BYTES (BM * LDA * 2)            // 18432
#define B_STAGE_BYTES (BK * LDB * 2)            // 33792
#define STAGE_BYTES (A_STAGE_BYTES + B_STAGE_BYTES)   // 52224
#define SMEM_TOTAL (STAGES * STAGE_BYTES)       // 208896 (< 227KB)

// Scratch (allocation-free rule: __device__ globals)
__device__ __half WH[(size_t)K_TOT * N_TOT];   // dequantized weight (K,N) n-major
__device__ __half XH[(size_t)M_TOT * K_TOT];   // fp16 activations (M,K) k-major

// ---------------------------------------------------------------------------
// Dequant -> WH[k][n]
// ---------------------------------------------------------------------------
__global__ void dequant_kernel(const int* __restrict__ qweight,
                               const int* __restrict__ qzeros,
                               const int* __restrict__ qscales,
                               const float* __restrict__ qs_zeros,
                               const float* __restrict__ qs_scales,
                               const int* __restrict__ g_idx) {
    int idx = blockIdx.x * blockDim.x + threadIdx.x;   // over (K/8)*N
    int n  = idx % N_TOT;
    int kw = idx / N_TOT;
    if (kw >= K_TOT / 8) return;

    int g = g_idx[kw * 8];                              // 8 | 32 -> same group
    int zw = qzeros[g * (N_TOT / 8) + (n >> 3)];
    int z  = ((zw >> ((n & 7) * 4)) & 0xF) + 1;
    float scale = ((float)qscales[g * N_TOT + n] - qs_zeros[g]) * qs_scales[g];
    int w = qweight[kw * N_TOT + n];

#pragma unroll
    for (int j = 0; j < 8; ++j) {
        int nib = (w >> (4 * j)) & 0xF;
        WH[(size_t)(kw * 8 + j) * N_TOT + n] =
            __float2half_rn((float)(nib - z) * scale);
    }
}

// ---------------------------------------------------------------------------
__global__ void xconv_kernel(const float* __restrict__ x) {
    size_t i = ((size_t)blockIdx.x * blockDim.x + threadIdx.x) * 4;
    float4 v = *(const float4*)(x + i);
    *(__half2*)(XH + i)     = __floats2half2_rn(v.x, v.y);
    *(__half2*)(XH + i + 2) = __floats2half2_rn(v.z, v.w);
}

// ---------------------------------------------------------------------------
__device__ __forceinline__ uint32_t smem_u32(const void* p) {
    return (uint32_t)__cvta_generic_to_shared(p);
}
__device__ __forceinline__ void cp_async16(uint32_t s, const void* g) {
    asm volatile("cp.async.cg.shared.global [%0], [%1], 16;\n" :: "r"(s), "l"(g));
}
__device__ __forceinline__ void cp_commit() {
    asm volatile("cp.async.commit_group;\n" ::: "memory");
}
template <int Ngrp>
__device__ __forceinline__ void cp_wait() {
    asm volatile("cp.async.wait_group %0;\n" :: "n"(Ngrp) : "memory");
}

// ---------------------------------------------------------------------------
// fp16 GEMM, fp32 accum: out(M,N) = XH(M,K) @ WH(K,N)
// BM=128 BN=256 BK=64, 8 warps @ 64x64 warp tiles, 4-stage cp.async ring
// ---------------------------------------------------------------------------
__global__ __launch_bounds__(256, 1)
void gemm_kernel(float* __restrict__ out) {
    extern __shared__ __align__(16) char sm[];
    const uint32_t smb = smem_u32(sm);

    const int tid  = threadIdx.x;
    const int warp = tid >> 5;
    const int lane = tid & 31;
    const int bm = blockIdx.y * BM;
    const int bn = blockIdx.x * BN;
    const int wm = (warp >> 2) * 64;    // 0 / 64
    const int wn = (warp & 3) * 64;     // 0 / 64 / 128 / 192

    float acc[4][8][4];
#pragma unroll
    for (int mi = 0; mi < 4; ++mi)
#pragma unroll
        for (int ni = 0; ni < 8; ++ni)
#pragma unroll
            for (int r = 0; r < 4; ++r) acc[mi][ni][r] = 0.f;

    // A: 128 rows x 8 chunks (16B) each; B: 64 rows x 32 chunks
    auto prefetch = [&](int s, int k0) {
        const uint32_t Ab = smb + s * STAGE_BYTES;
        const uint32_t Bb = Ab + A_STAGE_BYTES;
#pragma unroll
        for (int i = 0; i < 4; ++i) {
            int c = tid + i * 256;
            int row = c >> 3, col = (c & 7) * 8;
            cp_async16(Ab + row * (LDA * 2) + col * 2,
                       XH + (size_t)(bm + row) * K_TOT + k0 + col);
        }
#pragma unroll
        for (int i = 0; i < 8; ++i) {
            int c = tid + i * 256;
            int row = c >> 5, col = (c & 31) * 8;
            cp_async16(Bb + row * (LDB * 2) + col * 2,
                       WH + (size_t)(k0 + row) * N_TOT + bn + col);
        }
        cp_commit();
    };

    prefetch(0, 0);
    prefetch(1, BK);
    prefetch(2, 2 * BK);

    for (int kt = 0; kt < NT; ++kt) {
        if (kt + 3 < NT) prefetch((kt + 3) & 3, (kt + 3) * BK);
        else             cp_commit();          // keep group count uniform
        cp_wait<3>();                          // group kt landed
        __syncthreads();

        const uint32_t Ab = smb + (kt & 3) * STAGE_BYTES;
        const uint32_t Bb = Ab + A_STAGE_BYTES;

#pragma unroll
        for (int ks = 0; ks < 4; ++ks) {
            uint32_t a[4][4];
#pragma unroll
            for (int mi = 0; mi < 4; ++mi) {
                uint32_t addr = Ab + (wm + mi * 16 + (lane & 15)) * (LDA * 2)
                              + (ks * 16 + (lane >> 4) * 8) * 2;
                asm volatile(
                    "ldmatrix.sync.aligned.m8n8.x4.shared.b16 {%0,%1,%2,%3}, [%4];\n"
                    : "=r"(a[mi][0]), "=r"(a[mi][1]), "=r"(a[mi][2]), "=r"(a[mi][3])
                    : "r"(addr));
            }
            uint32_t b[8][2];
#pragma unroll
            for (int ni = 0; ni < 8; ++ni) {
                uint32_t addr = Bb + (ks * 16 + (lane & 15)) * (LDB * 2)
                              + (wn + ni * 8) * 2;
                asm volatile(
                    "ldmatrix.sync.aligned.m8n8.x2.trans.shared.b16 {%0,%1}, [%2];\n"
                    : "=r"(b[ni][0]), "=r"(b[ni][1])
                    : "r"(addr));
            }
#pragma unroll
            for (int mi = 0; mi < 4; ++mi)
#pragma unroll
                for (int ni = 0; ni < 8; ++ni) {
                    asm volatile(
                        "mma.sync.aligned.m16n8k16.row.col.f32.f16.f16.f32 "
                        "{%0,%1,%2,%3}, {%4,%5,%6,%7}, {%8,%9}, {%0,%1,%2,%3};\n"
                        : "+f"(acc[mi][ni][0]), "+f"(acc[mi][ni][1]),
                          "+f"(acc[mi][ni][2]), "+f"(acc[mi][ni][3])
                        : "r"(a[mi][0]), "r"(a[mi][1]), "r"(a[mi][2]), "r"(a[mi][3]),
                          "r"(b[ni][0]), "r"(b[ni][1]));
                }
        }
        __syncthreads();                       // readers done before slot reuse
    }

    // Epilogue: m16n8 frag -> rows lane/4, lane/4+8; cols 2*(lane%4)+{0,1}
    const int r0 = lane >> 2;
    const int c0 = (lane & 3) * 2;
#pragma unroll
    for (int mi = 0; mi < 4; ++mi)
#pragma unroll
        for (int ni = 0; ni < 8; ++ni) {
            size_t base = (size_t)(bm + wm + mi * 16) * N_TOT + bn + wn + ni * 8;
            *(float2*)&out[base + (size_t)r0 * N_TOT + c0] =
                make_float2(acc[mi][ni][0], acc[mi][ni][1]);
            *(float2*)&out[base + (size_t)(r0 + 8) * N_TOT + c0] =
                make_float2(acc[mi][ni][2], acc[mi][ni][3]);
        }
}

// ---------------------------------------------------------------------------
extern "C" void kernel_launch(void* const* d_in, const int* in_sizes, int n_in,
                              void* d_out, int out_size) {
    const float* x        = (const float*)d_in[0];
    const int*   qweight  = (const int*)d_in[1];
    const int*   qzeros   = (const int*)d_in[2];
    const int*   qscales  = (const int*)d_in[3];
    const float* qsz      = (const float*)d_in[4];
    const float* qss      = (const float*)d_in[5];
    const int*   g_idx    = (const int*)d_in[6];
    float*       out      = (float*)d_out;

    {
        int total = (K_TOT / 8) * N_TOT;
        dequant_kernel<<<(total + 255) / 256, 256>>>(qweight, qzeros, qscales,
                                                     qsz, qss, g_idx);
    }
    {
        size_t total = (size_t)M_TOT * K_TOT / 4;
        xconv_kernel<<<(unsigned)(total / 256), 256>>>(x);
    }
    {
        cudaFuncSetAttribute(gemm_kernel,
                             cudaFuncAttributeMaxDynamicSharedMemorySize, SMEM_TOTAL);
        dim3 grid(N_TOT / BN, M_TOT / BM);    // (16, 64)
        gemm_kernel<<<grid, 256, SMEM_TOTAL>>>(out);
    }
}

// round 12
// speedup vs baseline: 1.0622x; 1.0622x over previous
#include <cuda_runtime.h>
#include <cuda_fp16.h>
#include <cstdint>

#define M_TOT 8192
#define N_TOT 4096
#define K_TOT 4096

#define BM 128
#define BN 128
#define BK 64
#define NT (K_TOT / BK)          // 64
#define STAGES 3

#define LDA 72                   // 64+8 halves; 144B = 9*16B odd -> conflict-free
#define LDB 136                  // 128+8 halves; 272B = 17*16B odd -> conflict-free
#define A_STAGE_BYTES (BM * LDA * 2)            // 18432
#define B_STAGE_BYTES (BK * LDB * 2)            // 17408
#define STAGE_BYTES (A_STAGE_BYTES + B_STAGE_BYTES)   // 35840
#define SMEM_TOTAL (STAGES * STAGE_BYTES)       // 107520 -> 2 CTAs/SM

// Scratch (allocation-free rule: __device__ globals)
__device__ __half WH[(size_t)K_TOT * N_TOT];   // dequantized weight (K,N) n-major
__device__ __half XH[(size_t)M_TOT * K_TOT];   // fp16 activations (M,K) k-major

#define DQ_BLOCKS ((K_TOT / 8) * N_TOT / 256)          // 8192
#define XC_BLOCKS ((size_t)M_TOT * K_TOT / 4 / 256)    // 32768

// ---------------------------------------------------------------------------
// Fused prep: blocks [0, DQ_BLOCKS) dequant -> WH ; rest convert x -> XH
// ---------------------------------------------------------------------------
__global__ void prep_kernel(const float* __restrict__ x,
                            const int* __restrict__ qweight,
                            const int* __restrict__ qzeros,
                            const int* __restrict__ qscales,
                            const float* __restrict__ qs_zeros,
                            const float* __restrict__ qs_scales,
                            const int* __restrict__ g_idx) {
    if (blockIdx.x < DQ_BLOCKS) {
        int idx = blockIdx.x * 256 + threadIdx.x;      // over (K/8)*N
        int n  = idx % N_TOT;
        int kw = idx / N_TOT;

        int g = g_idx[kw * 8];                          // 8 | 32 -> same group
        int zw = qzeros[g * (N_TOT / 8) + (n >> 3)];
        int z  = ((zw >> ((n & 7) * 4)) & 0xF) + 1;
        float scale = ((float)qscales[g * N_TOT + n] - qs_zeros[g]) * qs_scales[g];
        int w = qweight[kw * N_TOT + n];

#pragma unroll
        for (int j = 0; j < 8; ++j) {
            int nib = (w >> (4 * j)) & 0xF;
            WH[(size_t)(kw * 8 + j) * N_TOT + n] =
                __float2half_rn((float)(nib - z) * scale);
        }
    } else {
        size_t i = (((size_t)blockIdx.x - DQ_BLOCKS) * 256 + threadIdx.x) * 4;
        float4 v = *(const float4*)(x + i);
        *(__half2*)(XH + i)     = __floats2half2_rn(v.x, v.y);
        *(__half2*)(XH + i + 2) = __floats2half2_rn(v.z, v.w);
    }
}

// ---------------------------------------------------------------------------
__device__ __forceinline__ uint32_t smem_u32(const void* p) {
    return (uint32_t)__cvta_generic_to_shared(p);
}
__device__ __forceinline__ void cp_async16(uint32_t s, const void* g) {
    asm volatile("cp.async.cg.shared.global [%0], [%1], 16;\n" :: "r"(s), "l"(g));
}
__device__ __forceinline__ void cp_commit() {
    asm volatile("cp.async.commit_group;\n" ::: "memory");
}
template <int Ngrp>
__device__ __forceinline__ void cp_wait() {
    asm volatile("cp.async.wait_group %0;\n" :: "n"(Ngrp) : "memory");
}

// ---------------------------------------------------------------------------
// fp16 GEMM, fp32 accum: out(M,N) = XH(M,K) @ WH(K,N)
// BM=BN=128, BK=64, 8 warps @ 64x32 warp tiles, 3-stage cp.async ring,
// 2 CTAs/SM (the config that saturates the legacy HMMA pipe).
// ---------------------------------------------------------------------------
__global__ __launch_bounds__(256, 2)
void gemm_kernel(float* __restrict__ out) {
    extern __shared__ __align__(16) char sm[];
    const uint32_t smb = smem_u32(sm);

    const int tid  = threadIdx.x;
    const int warp = tid >> 5;
    const int lane = tid & 31;
    const int bm = blockIdx.y * BM;
    const int bn = blockIdx.x * BN;
    const int wm = (warp >> 2) * 64;    // 0 / 64
    const int wn = (warp & 3) * 32;     // 0 / 32 / 64 / 96

    float acc[4][4][4];
#pragma unroll
    for (int mi = 0; mi < 4; ++mi)
#pragma unroll
        for (int ni = 0; ni < 4; ++ni)
#pragma unroll
            for (int r = 0; r < 4; ++r) acc[mi][ni][r] = 0.f;

    // A: 128 rows x 8 chunks(16B) = 1024 chunks; B: 64 rows x 16 chunks = 1024
    auto prefetch = [&](int s, int k0) {
        const uint32_t Ab = smb + s * STAGE_BYTES;
        const uint32_t Bb = Ab + A_STAGE_BYTES;
#pragma unroll
        for (int i = 0; i < 4; ++i) {
            int c = tid + i * 256;
            int row = c >> 3, col = (c & 7) * 8;
            cp_async16(Ab + row * (LDA * 2) + col * 2,
                       XH + (size_t)(bm + row) * K_TOT + k0 + col);
        }
#pragma unroll
        for (int i = 0; i < 4; ++i) {
            int c = tid + i * 256;
            int row = c >> 4, col = (c & 15) * 8;
            cp_async16(Bb + row * (LDB * 2) + col * 2,
                       WH + (size_t)(k0 + row) * N_TOT + bn + col);
        }
        cp_commit();
    };

    prefetch(0, 0);
    prefetch(1, BK);

    int buf = 0;
    for (int kt = 0; kt < NT; ++kt) {
        if (kt + 2 < NT) {
            int s = buf + 2; if (s >= STAGES) s -= STAGES;
            prefetch(s, (kt + 2) * BK);
        } else {
            cp_commit();                       // keep group count uniform
        }
        cp_wait<2>();                          // group kt landed
        __syncthreads();

        const uint32_t Ab = smb + buf * STAGE_BYTES;
        const uint32_t Bb = Ab + A_STAGE_BYTES;

#pragma unroll
        for (int ks = 0; ks < 4; ++ks) {
            uint32_t a[4][4];
#pragma unroll
            for (int mi = 0; mi < 4; ++mi) {
                uint32_t addr = Ab + (wm + mi * 16 + (lane & 15)) * (LDA * 2)
                              + (ks * 16 + (lane >> 4) * 8) * 2;
                asm volatile(
                    "ldmatrix.sync.aligned.m8n8.x4.shared.b16 {%0,%1,%2,%3}, [%4];\n"
                    : "=r"(a[mi][0]), "=r"(a[mi][1]), "=r"(a[mi][2]), "=r"(a[mi][3])
                    : "r"(addr));
            }
            uint32_t b[4][2];
#pragma unroll
            for (int ni = 0; ni < 4; ++ni) {
                uint32_t addr = Bb + (ks * 16 + (lane & 15)) * (LDB * 2)
                              + (wn + ni * 8) * 2;
                asm volatile(
                    "ldmatrix.sync.aligned.m8n8.x2.trans.shared.b16 {%0,%1}, [%2];\n"
                    : "=r"(b[ni][0]), "=r"(b[ni][1])
                    : "r"(addr));
            }
#pragma unroll
            for (int mi = 0; mi < 4; ++mi)
#pragma unroll
                for (int ni = 0; ni < 4; ++ni) {
                    asm volatile(
                        "mma.sync.aligned.m16n8k16.row.col.f32.f16.f16.f32 "
                        "{%0,%1,%2,%3}, {%4,%5,%6,%7}, {%8,%9}, {%0,%1,%2,%3};\n"
                        : "+f"(acc[mi][ni][0]), "+f"(acc[mi][ni][1]),
                          "+f"(acc[mi][ni][2]), "+f"(acc[mi][ni][3])
                        : "r"(a[mi][0]), "r"(a[mi][1]), "r"(a[mi][2]), "r"(a[mi][3]),
                          "r"(b[ni][0]), "r"(b[ni][1]));
                }
        }
        __syncthreads();                       // readers done before ring reuse
        if (++buf == STAGES) buf = 0;
    }

    // Epilogue: m16n8 frag -> rows lane/4, lane/4+8; cols 2*(lane%4)+{0,1}
    const int r0 = lane >> 2;
    const int c0 = (lane & 3) * 2;
#pragma unroll
    for (int mi = 0; mi < 4; ++mi)
#pragma unroll
        for (int ni = 0; ni < 4; ++ni) {
            size_t base = (size_t)(bm + wm + mi * 16) * N_TOT + bn + wn + ni * 8;
            *(float2*)&out[base + (size_t)r0 * N_TOT + c0] =
                make_float2(acc[mi][ni][0], acc[mi][ni][1]);
            *(float2*)&out[base + (size_t)(r0 + 8) * N_TOT + c0] =
                make_float2(acc[mi][ni][2], acc[mi][ni][3]);
        }
}

// ---------------------------------------------------------------------------
extern "C" void kernel_launch(void* const* d_in, const int* in_sizes, int n_in,
                              void* d_out, int out_size) {
    const float* x        = (const float*)d_in[0];
    const int*   qweight  = (const int*)d_in[1];
    const int*   qzeros   = (const int*)d_in[2];
    const int*   qscales  = (const int*)d_in[3];
    const float* qsz      = (const float*)d_in[4];
    const float* qss      = (const float*)d_in[5];
    const int*   g_idx    = (const int*)d_in[6];
    float*       out      = (float*)d_out;

    {
        unsigned grid = (unsigned)(DQ_BLOCKS + XC_BLOCKS);   // 40960
        prep_kernel<<<grid, 256>>>(x, qweight, qzeros, qscales, qsz, qss, g_idx);
    }
    {
        cudaFuncSetAttribute(gemm_kernel,
                             cudaFuncAttributeMaxDynamicSharedMemorySize, SMEM_TOTAL);
        dim3 grid(N_TOT / BN, M_TOT / BM);    // (32, 64)
        gemm_kernel<<<grid, 256, SMEM_TOTAL>>>(out);
    }
}